// round 13
// baseline (speedup 1.0000x reference)
#include <cuda_runtime.h>
#include <cuda_bf16.h>
#include <math.h>

// ---------------- problem constants ----------------
#define CH 192
#define HEADS 6
#define MTOT 131072
#define HIDDEN 768

// ---------------- scratch ----------------
__device__ __nv_bfloat16 gb_xn  [(size_t)MTOT * CH];
__device__ __nv_bfloat16 gb_qkv [(size_t)MTOT * 3 * CH];
__device__ __nv_bfloat16 gb_attn[(size_t)MTOT * CH];
__device__ float         g_x1   [(size_t)MTOT * CH];
__device__ __nv_bfloat16 gb_h2  [(size_t)MTOT * CH];
__device__ __nv_bfloat16 gb_hid [(size_t)MTOT * HIDDEN];
__device__ __nv_bfloat16 gb_w[576*192 + 192*192 + 768*192 + 192*768];

__device__ __forceinline__ int gather_row(int m) {
    int win = m >> 6, n = m & 63;
    int b   = win >> 10, rem = win & 1023;
    int wh  = rem >> 5,  ww  = rem & 31;
    int r   = n >> 3,    c   = n & 7;
    int hs  = (wh * 8 + r + 4) & 255;
    int ws_ = (ww * 8 + c + 4) & 255;
    return (b << 16) | (hs << 8) | ws_;
}

__device__ __forceinline__ unsigned smem_u32(const void* p) {
    return (unsigned)__cvta_generic_to_shared(p);
}

// ---------------- all weights fp32 -> bf16, ONE launch ----------------
#define WQ_SZ  110592
#define WP_SZ  36864
#define W1_SZ  147456
#define W2_SZ  147456
#define WTOT   (WQ_SZ + WP_SZ + W1_SZ + W2_SZ)

__global__ void wconv_all(const float* __restrict__ qkv_w, const float* __restrict__ proj_w,
                          const float* __restrict__ w1,    const float* __restrict__ w2,
                          __nv_bfloat16* __restrict__ out) {
    int i = blockIdx.x * 256 + threadIdx.x;
    if (i >= WTOT) return;
    const float* src; int off;
    if (i < WQ_SZ)                 { src = qkv_w;  off = i; }
    else if (i < WQ_SZ + WP_SZ)    { src = proj_w; off = i - WQ_SZ; }
    else if (i < WQ_SZ + WP_SZ + W1_SZ) { src = w1; off = i - WQ_SZ - WP_SZ; }
    else                           { src = w2;     off = i - WQ_SZ - WP_SZ - W1_SZ; }
    out[i] = __float2bfloat16(src[off]);
}

// ---------------- LayerNorm: one warp per row of 192, bf16 out ----------------
__global__ void ln_kernel(const float* __restrict__ in, const float* __restrict__ g,
                          const float* __restrict__ b, __nv_bfloat16* __restrict__ out, int M) {
    int row  = blockIdx.x * (blockDim.x >> 5) + (threadIdx.x >> 5);
    int lane = threadIdx.x & 31;
    if (row >= M) return;
    const float* rp = in + (size_t)row * CH;
    float v[6];
    float s = 0.f;
#pragma unroll
    for (int i = 0; i < 6; i++) { v[i] = rp[lane + 32 * i]; s += v[i]; }
#pragma unroll
    for (int o = 16; o; o >>= 1) s += __shfl_xor_sync(0xffffffffu, s, o);
    float mean = s * (1.f / 192.f);
    float q = 0.f;
#pragma unroll
    for (int i = 0; i < 6; i++) { float d = v[i] - mean; q += d * d; }
#pragma unroll
    for (int o = 16; o; o >>= 1) q += __shfl_xor_sync(0xffffffffu, q, o);
    float inv = rsqrtf(q * (1.f / 192.f) + 1e-5f);
    __nv_bfloat16* op = out + (size_t)row * CH;
#pragma unroll
    for (int i = 0; i < 6; i++) {
        int col = lane + 32 * i;
        op[col] = __float2bfloat16((v[i] - mean) * inv * g[col] + b[col]);
    }
}

// ---------------- HMMA bf16 GEMM: 128x96 CTA tile, 6 warps (2M x 3N), 4-stage cp.async ----------------
// All N dims divide 96 exactly: 576=6*96, 192=2*96, 768=8*96 -> zero tile waste.
// C[m,n] = sum_k A[m,k]*W[n,k]
// EPI: 0 = store bf16; 1 = +bias, exact GELU, bf16; 2 = scatter row, +res[gathered], fp32; 3 = +bias, +res[m], fp32
#define KSTEP 32
#define SPAD 40
#define NT 96
#define NSTG 4

template<int EPI, bool GATHER>
__global__ void __launch_bounds__(192, 3) gemm_mma(
    const __nv_bfloat16* __restrict__ A, const __nv_bfloat16* __restrict__ W,
    const float* __restrict__ bias, const float* __restrict__ res,
    void* __restrict__ Cout, int K, int N)
{
    __shared__ __nv_bfloat16 As[NSTG][128][SPAD];
    __shared__ __nv_bfloat16 Bs[NSTG][NT][SPAD];
    const int m0 = blockIdx.x * 128, n0 = blockIdx.y * NT;
    const int t = threadIdx.x, lane = t & 31, wid = t >> 5;
    const int wm = wid & 1, wn = wid >> 1;   // 2(M) x 3(N) warps, each 64x32

    // loaders: warps 0-3 (t<128) load A row t; warps 4-5 load B rows (u, and u+64 if u<32)
    const bool isA = (t < 128);
    const int  u   = t - 128;                          // 0..63 for B threads
    const int  arow = GATHER ? gather_row(m0 + (t & 127)) : (m0 + (t & 127));
    const __nv_bfloat16* Ap  = A + (size_t)arow * K;
    int bg0 = n0 + (u & 63);        if (bg0 >= N) bg0 = 0;
    int bg1 = n0 + 64 + (u & 31);   if (bg1 >= N) bg1 = 0;
    const __nv_bfloat16* Wp0 = W + (size_t)bg0 * K;
    const __nv_bfloat16* Wp1 = W + (size_t)bg1 * K;

    float acc[4][4][4];
#pragma unroll
    for (int i = 0; i < 4; i++)
#pragma unroll
        for (int j = 0; j < 4; j++)
#pragma unroll
            for (int q = 0; q < 4; q++) acc[i][j][q] = 0.f;

    const int nk = K / KSTEP;   // 6 (K=192) or 24 (K=768)

#define LOAD_STAGE(st, ks)                                                                    \
    do {                                                                                      \
        if (isA) {                                                                            \
            unsigned _d = smem_u32(&As[st][t][0]);                                            \
            const __nv_bfloat16* _p = Ap + (ks) * KSTEP;                                      \
            asm volatile("cp.async.cg.shared.global [%0], [%1], 16;\n" :: "r"(_d),      "l"(_p));      \
            asm volatile("cp.async.cg.shared.global [%0], [%1], 16;\n" :: "r"(_d + 16), "l"(_p + 8));  \
            asm volatile("cp.async.cg.shared.global [%0], [%1], 16;\n" :: "r"(_d + 32), "l"(_p + 16)); \
            asm volatile("cp.async.cg.shared.global [%0], [%1], 16;\n" :: "r"(_d + 48), "l"(_p + 24)); \
        } else {                                                                              \
            unsigned _d0 = smem_u32(&Bs[st][u][0]);                                           \
            const __nv_bfloat16* _p0 = Wp0 + (ks) * KSTEP;                                    \
            asm volatile("cp.async.cg.shared.global [%0], [%1], 16;\n" :: "r"(_d0),      "l"(_p0));      \
            asm volatile("cp.async.cg.shared.global [%0], [%1], 16;\n" :: "r"(_d0 + 16), "l"(_p0 + 8));  \
            asm volatile("cp.async.cg.shared.global [%0], [%1], 16;\n" :: "r"(_d0 + 32), "l"(_p0 + 16)); \
            asm volatile("cp.async.cg.shared.global [%0], [%1], 16;\n" :: "r"(_d0 + 48), "l"(_p0 + 24)); \
            if (u < 32) {                                                                     \
                unsigned _d1 = smem_u32(&Bs[st][64 + u][0]);                                  \
                const __nv_bfloat16* _p1 = Wp1 + (ks) * KSTEP;                                \
                asm volatile("cp.async.cg.shared.global [%0], [%1], 16;\n" :: "r"(_d1),      "l"(_p1));      \
                asm volatile("cp.async.cg.shared.global [%0], [%1], 16;\n" :: "r"(_d1 + 16), "l"(_p1 + 8));  \
                asm volatile("cp.async.cg.shared.global [%0], [%1], 16;\n" :: "r"(_d1 + 32), "l"(_p1 + 16)); \
                asm volatile("cp.async.cg.shared.global [%0], [%1], 16;\n" :: "r"(_d1 + 48), "l"(_p1 + 24)); \
            }                                                                                 \
        }                                                                                     \
        asm volatile("cp.async.commit_group;\n");                                             \
    } while (0)

    // prefetch 3 stages ahead
    LOAD_STAGE(0, 0);
    LOAD_STAGE(1, 1);
    LOAD_STAGE(2, 2);

    const int r16 = lane & 15, chh = lane >> 4;

    for (int ks = 0; ks < nk; ks++) {
        if (ks + 2 < nk)      asm volatile("cp.async.wait_group 2;\n");
        else if (ks + 1 < nk) asm volatile("cp.async.wait_group 1;\n");
        else                  asm volatile("cp.async.wait_group 0;\n");
        __syncthreads();

        if (ks + 3 < nk) {
            int st = (ks + 3) % NSTG;
            LOAD_STAGE(st, ks + 3);
        }

        const int buf = ks % NSTG;
#pragma unroll
        for (int kk = 0; kk < 2; kk++) {
            unsigned a[4][4], b[2][4];
#pragma unroll
            for (int i = 0; i < 4; i++) {
                unsigned addr = smem_u32(&As[buf][wm * 64 + i * 16 + r16][kk * 16 + chh * 8]);
                asm volatile("ldmatrix.sync.aligned.m8n8.x4.shared.b16 {%0,%1,%2,%3}, [%4];"
                    : "=r"(a[i][0]), "=r"(a[i][1]), "=r"(a[i][2]), "=r"(a[i][3]) : "r"(addr));
            }
#pragma unroll
            for (int j2 = 0; j2 < 2; j2++) {
                unsigned addr = smem_u32(&Bs[buf][wn * 32 + j2 * 16 + r16][kk * 16 + chh * 8]);
                asm volatile("ldmatrix.sync.aligned.m8n8.x4.shared.b16 {%0,%1,%2,%3}, [%4];"
                    : "=r"(b[j2][0]), "=r"(b[j2][1]), "=r"(b[j2][2]), "=r"(b[j2][3]) : "r"(addr));
            }
#pragma unroll
            for (int i = 0; i < 4; i++)
#pragma unroll
                for (int j = 0; j < 4; j++) {
                    unsigned b0 = b[j >> 1][j & 1], b1 = b[j >> 1][(j & 1) + 2];
                    asm volatile(
                        "mma.sync.aligned.m16n8k16.row.col.f32.bf16.bf16.f32 "
                        "{%0,%1,%2,%3}, {%4,%5,%6,%7}, {%8,%9}, {%0,%1,%2,%3};"
                        : "+f"(acc[i][j][0]), "+f"(acc[i][j][1]), "+f"(acc[i][j][2]), "+f"(acc[i][j][3])
                        : "r"(a[i][0]), "r"(a[i][1]), "r"(a[i][2]), "r"(a[i][3]), "r"(b0), "r"(b1));
                }
        }
    }
#undef LOAD_STAGE

    // epilogue: warp tile 64x32 at col n0 + wn*32
#pragma unroll
    for (int i = 0; i < 4; i++) {
        int rbase = m0 + wm * 64 + i * 16 + (lane >> 2);
#pragma unroll
        for (int j = 0; j < 4; j++) {
            int c = n0 + wn * 32 + j * 8 + (lane & 3) * 2;
            if (c < N) {
#pragma unroll
                for (int h = 0; h < 2; h++) {
                    int r = rbase + h * 8;
                    float v0 = acc[i][j][h * 2 + 0];
                    float v1 = acc[i][j][h * 2 + 1];
                    if (bias) { v0 += __ldg(&bias[c]); v1 += __ldg(&bias[c + 1]); }
                    if (EPI == 1) {
                        v0 = 0.5f * v0 * (1.f + erff(v0 * 0.70710678118654752f));
                        v1 = 0.5f * v1 * (1.f + erff(v1 * 0.70710678118654752f));
                    }
                    if (EPI >= 2) {
                        int orow = (EPI == 2) ? gather_row(r) : r;
                        size_t off = (size_t)orow * N + c;
                        float2 rv = *(const float2*)(res + off);
                        float2 ov; ov.x = v0 + rv.x; ov.y = v1 + rv.y;
                        *(float2*)((float*)Cout + off) = ov;
                    } else {
                        __nv_bfloat162 p;
                        p.x = __float2bfloat16(v0); p.y = __float2bfloat16(v1);
                        *(__nv_bfloat162*)((__nv_bfloat16*)Cout + (size_t)r * N + c) = p;
                    }
                }
            }
        }
    }
}

// ---------------- tensor-core windowed attention (R9, unchanged) ----------------
__device__ __forceinline__ int region(int p) { return p < 248 ? 0 : (p < 252 ? 1 : 2); }

__global__ void __launch_bounds__(128) attn_kernel(const __nv_bfloat16* __restrict__ qkv,
                                                   const float* __restrict__ rpb,
                                                   __nv_bfloat16* __restrict__ out) {
    __shared__ __nv_bfloat16 Qs[64][40];
    __shared__ __nv_bfloat16 Ks[64][40];
    __shared__ __nv_bfloat16 Vs[64][40];
    __shared__ float srpb[225];
    __shared__ int   sreg[64];

    const int win = blockIdx.x, h = blockIdx.y;
    const int t = threadIdx.x, lane = t & 31, warp = t >> 5;
    const float scale = 0.17677669529663687f;

    for (int i = t; i < 225; i += 128) srpb[i] = rpb[i * HEADS + h];
    if (t < 64) {
        int rem = win & 1023;
        int wh = rem >> 5, ww = rem & 31;
        sreg[t] = region(wh * 8 + (t >> 3)) * 3 + region(ww * 8 + (t & 7));
    }
#pragma unroll
    for (int it = 0; it < 2; it++) {
        int c = t + it * 128;
        int row = c >> 2, off = (c & 3) * 8;
        const __nv_bfloat16* src = qkv + (size_t)(win * 64 + row) * 576 + h * 32 + off;
        *(uint4*)&Qs[row][off] = *(const uint4*)(src);
        *(uint4*)&Ks[row][off] = *(const uint4*)(src + 192);
        *(uint4*)&Vs[row][off] = *(const uint4*)(src + 384);
    }
    __syncthreads();

    unsigned qa[2][4], kb[4][2][4];
    const int r16 = lane & 15, chh = lane >> 4;
#pragma unroll
    for (int kt = 0; kt < 2; kt++) {
        unsigned addr = smem_u32(&Qs[warp * 16 + r16][chh * 8 + kt * 16]);
        asm volatile("ldmatrix.sync.aligned.m8n8.x4.shared.b16 {%0,%1,%2,%3}, [%4];"
            : "=r"(qa[kt][0]), "=r"(qa[kt][1]), "=r"(qa[kt][2]), "=r"(qa[kt][3]) : "r"(addr));
    }
#pragma unroll
    for (int j2 = 0; j2 < 4; j2++)
#pragma unroll
        for (int kt = 0; kt < 2; kt++) {
            unsigned addr = smem_u32(&Ks[j2 * 16 + r16][chh * 8 + kt * 16]);
            asm volatile("ldmatrix.sync.aligned.m8n8.x4.shared.b16 {%0,%1,%2,%3}, [%4];"
                : "=r"(kb[j2][kt][0]), "=r"(kb[j2][kt][1]), "=r"(kb[j2][kt][2]), "=r"(kb[j2][kt][3]) : "r"(addr));
        }

    float s[8][4];
#pragma unroll
    for (int nt = 0; nt < 8; nt++) {
        s[nt][0] = s[nt][1] = s[nt][2] = s[nt][3] = 0.f;
        unsigned b0 = kb[nt >> 1][0][nt & 1], b1 = kb[nt >> 1][0][(nt & 1) + 2];
        asm volatile(
            "mma.sync.aligned.m16n8k16.row.col.f32.bf16.bf16.f32 "
            "{%0,%1,%2,%3}, {%4,%5,%6,%7}, {%8,%9}, {%0,%1,%2,%3};"
            : "+f"(s[nt][0]), "+f"(s[nt][1]), "+f"(s[nt][2]), "+f"(s[nt][3])
            : "r"(qa[0][0]), "r"(qa[0][1]), "r"(qa[0][2]), "r"(qa[0][3]), "r"(b0), "r"(b1));
        b0 = kb[nt >> 1][1][nt & 1]; b1 = kb[nt >> 1][1][(nt & 1) + 2];
        asm volatile(
            "mma.sync.aligned.m16n8k16.row.col.f32.bf16.bf16.f32 "
            "{%0,%1,%2,%3}, {%4,%5,%6,%7}, {%8,%9}, {%0,%1,%2,%3};"
            : "+f"(s[nt][0]), "+f"(s[nt][1]), "+f"(s[nt][2]), "+f"(s[nt][3])
            : "r"(qa[1][0]), "r"(qa[1][1]), "r"(qa[1][2]), "r"(qa[1][3]), "r"(b0), "r"(b1));
    }

    const int qi0 = warp * 16 + (lane >> 2);
    const int qi1 = qi0 + 8;
    const int ri0 = qi0 >> 3, ci0 = qi0 & 7;
    const int ri1 = qi1 >> 3, ci1 = qi1 & 7;
    const int id0 = sreg[qi0], id1 = sreg[qi1];

    float mx0 = -1e30f, mx1 = -1e30f;
#pragma unroll
    for (int nt = 0; nt < 8; nt++) {
#pragma unroll
        for (int e = 0; e < 2; e++) {
            int j = nt * 8 + (lane & 3) * 2 + e;
            int rj = j >> 3, cj = j & 7, idj = sreg[j];
            float f0 = s[nt][e]     * scale + srpb[(ri0 - rj + 7) * 15 + (ci0 - cj + 7)];
            float f1 = s[nt][e + 2] * scale + srpb[(ri1 - rj + 7) * 15 + (ci1 - cj + 7)];
            if (id0 != idj) f0 -= 100.f;
            if (id1 != idj) f1 -= 100.f;
            s[nt][e] = f0; s[nt][e + 2] = f1;
            mx0 = fmaxf(mx0, f0); mx1 = fmaxf(mx1, f1);
        }
    }
    mx0 = fmaxf(mx0, __shfl_xor_sync(0xffffffffu, mx0, 1));
    mx0 = fmaxf(mx0, __shfl_xor_sync(0xffffffffu, mx0, 2));
    mx1 = fmaxf(mx1, __shfl_xor_sync(0xffffffffu, mx1, 1));
    mx1 = fmaxf(mx1, __shfl_xor_sync(0xffffffffu, mx1, 2));

    float sum0 = 0.f, sum1 = 0.f;
#pragma unroll
    for (int nt = 0; nt < 8; nt++) {
#pragma unroll
        for (int e = 0; e < 2; e++) {
            float e0 = __expf(s[nt][e]     - mx0);
            float e1 = __expf(s[nt][e + 2] - mx1);
            s[nt][e] = e0; s[nt][e + 2] = e1;
            sum0 += e0; sum1 += e1;
        }
    }
    sum0 += __shfl_xor_sync(0xffffffffu, sum0, 1);
    sum0 += __shfl_xor_sync(0xffffffffu, sum0, 2);
    sum1 += __shfl_xor_sync(0xffffffffu, sum1, 1);
    sum1 += __shfl_xor_sync(0xffffffffu, sum1, 2);
    float inv0 = 1.f / sum0, inv1 = 1.f / sum1;

    unsigned pa[4][4];
#pragma unroll
    for (int kt = 0; kt < 4; kt++) {
        __nv_bfloat162 p;
        p = __floats2bfloat162_rn(s[2 * kt][0],     s[2 * kt][1]);     pa[kt][0] = *(unsigned*)&p;
        p = __floats2bfloat162_rn(s[2 * kt][2],     s[2 * kt][3]);     pa[kt][1] = *(unsigned*)&p;
        p = __floats2bfloat162_rn(s[2 * kt + 1][0], s[2 * kt + 1][1]); pa[kt][2] = *(unsigned*)&p;
        p = __floats2bfloat162_rn(s[2 * kt + 1][2], s[2 * kt + 1][3]); pa[kt][3] = *(unsigned*)&p;
    }

    float o[4][4];
#pragma unroll
    for (int nt = 0; nt < 4; nt++) o[nt][0] = o[nt][1] = o[nt][2] = o[nt][3] = 0.f;
#pragma unroll
    for (int kt = 0; kt < 4; kt++) {
#pragma unroll
        for (int nt = 0; nt < 4; nt++) {
            unsigned addr = smem_u32(&Vs[kt * 16 + r16][nt * 8]);
            unsigned b0, b1;
            asm volatile("ldmatrix.sync.aligned.m8n8.x2.trans.shared.b16 {%0,%1}, [%2];"
                : "=r"(b0), "=r"(b1) : "r"(addr));
            asm volatile(
                "mma.sync.aligned.m16n8k16.row.col.f32.bf16.bf16.f32 "
                "{%0,%1,%2,%3}, {%4,%5,%6,%7}, {%8,%9}, {%0,%1,%2,%3};"
                : "+f"(o[nt][0]), "+f"(o[nt][1]), "+f"(o[nt][2]), "+f"(o[nt][3])
                : "r"(pa[kt][0]), "r"(pa[kt][1]), "r"(pa[kt][2]), "r"(pa[kt][3]), "r"(b0), "r"(b1));
        }
    }

    __nv_bfloat16* op = out + (size_t)(win * 64) * CH + h * 32;
#pragma unroll
    for (int nt = 0; nt < 4; nt++) {
        int col = nt * 8 + (lane & 3) * 2;
        __nv_bfloat162 p0 = __floats2bfloat162_rn(o[nt][0] * inv0, o[nt][1] * inv0);
        __nv_bfloat162 p1 = __floats2bfloat162_rn(o[nt][2] * inv1, o[nt][3] * inv1);
        *(__nv_bfloat162*)&op[(size_t)qi0 * CH + col] = p0;
        *(__nv_bfloat162*)&op[(size_t)qi1 * CH + col] = p1;
    }
}

// ---------------- launcher ----------------
extern "C" void kernel_launch(void* const* d_in, const int* in_sizes, int n_in,
                              void* d_out, int out_size) {
    const float* x       = (const float*)d_in[0];
    const float* norm1_g = (const float*)d_in[1];
    const float* norm1_b = (const float*)d_in[2];
    const float* qkv_w   = (const float*)d_in[3];
    const float* rpb     = (const float*)d_in[4];
    const float* proj_w  = (const float*)d_in[5];
    const float* proj_b  = (const float*)d_in[6];
    const float* norm2_g = (const float*)d_in[7];
    const float* norm2_b = (const float*)d_in[8];
    const float* mlp_w1  = (const float*)d_in[9];
    const float* mlp_b1  = (const float*)d_in[10];
    const float* mlp_w2  = (const float*)d_in[11];
    const float* mlp_b2  = (const float*)d_in[12];
    float* out = (float*)d_out;

    __nv_bfloat16 *xn, *qkvb, *attnb, *h2, *hid, *wbuf;
    float* x1;
    cudaGetSymbolAddress((void**)&xn,    gb_xn);
    cudaGetSymbolAddress((void**)&qkvb,  gb_qkv);
    cudaGetSymbolAddress((void**)&attnb, gb_attn);
    cudaGetSymbolAddress((void**)&x1,    g_x1);
    cudaGetSymbolAddress((void**)&h2,    gb_h2);
    cudaGetSymbolAddress((void**)&hid,   gb_hid);
    cudaGetSymbolAddress((void**)&wbuf,  gb_w);

    __nv_bfloat16* wq = wbuf;
    __nv_bfloat16* wp = wbuf + WQ_SZ;
    __nv_bfloat16* w1 = wp   + WP_SZ;
    __nv_bfloat16* w2 = w1   + W1_SZ;

    const int M  = MTOT;
    const int MB = M / 128;         // 1024
    const int LN_BLOCKS = M / 8;

    // 1: weight conversion
    wconv_all<<<(WTOT + 255) / 256, 256>>>(qkv_w, proj_w, mlp_w1, mlp_w2, wbuf);

    // 2: LN1 -> bf16
    ln_kernel<<<LN_BLOCKS, 256>>>(x, norm1_g, norm1_b, xn, M);

    // 3: QKV GEMM (gathered rows), N = 576 = 6 x 96 exact
    gemm_mma<0, true><<<dim3(MB, 6), 192>>>(xn, wq, nullptr, nullptr, qkvb, CH, 576);

    // 4: windowed attention
    attn_kernel<<<dim3(2048, HEADS), 128>>>(qkvb, rpb, attnb);

    // 5: proj + scatter + residual -> x1 (fp32), N = 192 = 2 x 96 exact
    gemm_mma<2, false><<<dim3(MB, 2), 192>>>(attnb, wp, proj_b, x, x1, CH, 192);

    // 6: LN2 -> bf16
    ln_kernel<<<LN_BLOCKS, 256>>>(x1, norm2_g, norm2_b, h2, M);

    // 7: MLP1 (bias + exact GELU) -> bf16, N = 768 = 8 x 96 exact
    gemm_mma<1, false><<<dim3(MB, 8), 192>>>(h2, w1, mlp_b1, nullptr, hid, CH, HIDDEN);

    // 8: MLP2 (bias + residual) -> fp32 out, N = 192 = 2 x 96 exact
    gemm_mma<3, false><<<dim3(MB, 2), 192>>>(hid, w2, mlp_b2, x1, out, HIDDEN, 192);
}

// round 14
// speedup vs baseline: 1.0017x; 1.0017x over previous
#include <cuda_runtime.h>
#include <cuda_bf16.h>
#include <math.h>

// ---------------- problem constants ----------------
#define CH 192
#define HEADS 6
#define MTOT 131072
#define HIDDEN 768

// ---------------- scratch ----------------
__device__ __nv_bfloat16 gb_xn  [(size_t)MTOT * CH];
__device__ __nv_bfloat16 gb_qkv [(size_t)MTOT * 3 * CH];
__device__ __nv_bfloat16 gb_attn[(size_t)MTOT * CH];
__device__ float         g_x1   [(size_t)MTOT * CH];
__device__ __nv_bfloat16 gb_h2  [(size_t)MTOT * CH];
__device__ __nv_bfloat16 gb_hid [(size_t)MTOT * HIDDEN];
__device__ __nv_bfloat16 gb_w[576*192 + 192*192 + 768*192 + 192*768];

__device__ __forceinline__ int gather_row(int m) {
    int win = m >> 6, n = m & 63;
    int b   = win >> 10, rem = win & 1023;
    int wh  = rem >> 5,  ww  = rem & 31;
    int r   = n >> 3,    c   = n & 7;
    int hs  = (wh * 8 + r + 4) & 255;
    int ws_ = (ww * 8 + c + 4) & 255;
    return (b << 16) | (hs << 8) | ws_;
}

__device__ __forceinline__ unsigned smem_u32(const void* p) {
    return (unsigned)__cvta_generic_to_shared(p);
}

// ---------------- all weights fp32 -> bf16, ONE launch ----------------
#define WQ_SZ  110592
#define WP_SZ  36864
#define W1_SZ  147456
#define W2_SZ  147456
#define WTOT   (WQ_SZ + WP_SZ + W1_SZ + W2_SZ)

__global__ void wconv_all(const float* __restrict__ qkv_w, const float* __restrict__ proj_w,
                          const float* __restrict__ w1,    const float* __restrict__ w2,
                          __nv_bfloat16* __restrict__ out) {
    int i = blockIdx.x * 256 + threadIdx.x;
    if (i >= WTOT) return;
    const float* src; int off;
    if (i < WQ_SZ)                 { src = qkv_w;  off = i; }
    else if (i < WQ_SZ + WP_SZ)    { src = proj_w; off = i - WQ_SZ; }
    else if (i < WQ_SZ + WP_SZ + W1_SZ) { src = w1; off = i - WQ_SZ - WP_SZ; }
    else                           { src = w2;     off = i - WQ_SZ - WP_SZ - W1_SZ; }
    out[i] = __float2bfloat16(src[off]);
}

// ---------------- LayerNorm: one warp per row of 192, bf16 out ----------------
__global__ void ln_kernel(const float* __restrict__ in, const float* __restrict__ g,
                          const float* __restrict__ b, __nv_bfloat16* __restrict__ out, int M) {
    int row  = blockIdx.x * (blockDim.x >> 5) + (threadIdx.x >> 5);
    int lane = threadIdx.x & 31;
    if (row >= M) return;
    const float* rp = in + (size_t)row * CH;
    float v[6];
    float s = 0.f;
#pragma unroll
    for (int i = 0; i < 6; i++) { v[i] = rp[lane + 32 * i]; s += v[i]; }
#pragma unroll
    for (int o = 16; o; o >>= 1) s += __shfl_xor_sync(0xffffffffu, s, o);
    float mean = s * (1.f / 192.f);
    float q = 0.f;
#pragma unroll
    for (int i = 0; i < 6; i++) { float d = v[i] - mean; q += d * d; }
#pragma unroll
    for (int o = 16; o; o >>= 1) q += __shfl_xor_sync(0xffffffffu, q, o);
    float inv = rsqrtf(q * (1.f / 192.f) + 1e-5f);
    __nv_bfloat16* op = out + (size_t)row * CH;
#pragma unroll
    for (int i = 0; i < 6; i++) {
        int col = lane + 32 * i;
        op[col] = __float2bfloat16((v[i] - mean) * inv * g[col] + b[col]);
    }
}

// ---------------- HMMA bf16 GEMM: 128x96 CTA tile, 6 warps (2M x 3N), k-step 48, 3-stage ----------------
// All N dims divide 96 exactly: 576=6*96, 192=2*96, 768=8*96 -> zero tile waste.
// C[m,n] = sum_k A[m,k]*W[n,k]
// EPI: 0 = store bf16; 1 = +bias, exact GELU, bf16; 2 = scatter row, +res[gathered], fp32; 3 = +bias, +res[m], fp32
#define KSTEP 48
#define SPAD 56      // 48 + 8 pad; 112B stride, 16B aligned, conflict-free ldmatrix phases
#define NT 96
#define NSTG 3

template<int EPI, bool GATHER>
__global__ void __launch_bounds__(192, 3) gemm_mma(
    const __nv_bfloat16* __restrict__ A, const __nv_bfloat16* __restrict__ W,
    const float* __restrict__ bias, const float* __restrict__ res,
    void* __restrict__ Cout, int K, int N)
{
    __shared__ __nv_bfloat16 As[NSTG][128][SPAD];
    __shared__ __nv_bfloat16 Bs[NSTG][NT][SPAD];
    const int m0 = blockIdx.x * 128, n0 = blockIdx.y * NT;
    const int t = threadIdx.x, lane = t & 31, wid = t >> 5;
    const int wm = wid & 1, wn = wid >> 1;   // 2(M) x 3(N) warps, each 64x32

    // loaders: warps 0-3 (t<128) load A row t; warps 4-5 load B rows (u, and u+64 if u<32)
    const bool isA = (t < 128);
    const int  u   = t - 128;
    const int  arow = GATHER ? gather_row(m0 + (t & 127)) : (m0 + (t & 127));
    const __nv_bfloat16* Ap  = A + (size_t)arow * K;
    int bg0 = n0 + (u & 63);        if (bg0 >= N) bg0 = 0;
    int bg1 = n0 + 64 + (u & 31);   if (bg1 >= N) bg1 = 0;
    const __nv_bfloat16* Wp0 = W + (size_t)bg0 * K;
    const __nv_bfloat16* Wp1 = W + (size_t)bg1 * K;

    float acc[4][4][4];
#pragma unroll
    for (int i = 0; i < 4; i++)
#pragma unroll
        for (int j = 0; j < 4; j++)
#pragma unroll
            for (int q = 0; q < 4; q++) acc[i][j][q] = 0.f;

    const int nk = K / KSTEP;   // 4 (K=192) or 16 (K=768)

#define CPA6(dst, src)                                                                          \
    do {                                                                                        \
        asm volatile("cp.async.cg.shared.global [%0], [%1], 16;\n" :: "r"(dst),      "l"(src));       \
        asm volatile("cp.async.cg.shared.global [%0], [%1], 16;\n" :: "r"(dst + 16), "l"(src + 8));   \
        asm volatile("cp.async.cg.shared.global [%0], [%1], 16;\n" :: "r"(dst + 32), "l"(src + 16));  \
        asm volatile("cp.async.cg.shared.global [%0], [%1], 16;\n" :: "r"(dst + 48), "l"(src + 24));  \
        asm volatile("cp.async.cg.shared.global [%0], [%1], 16;\n" :: "r"(dst + 64), "l"(src + 32));  \
        asm volatile("cp.async.cg.shared.global [%0], [%1], 16;\n" :: "r"(dst + 80), "l"(src + 40));  \
    } while (0)

#define LOAD_STAGE(st, ks)                                                                    \
    do {                                                                                      \
        if (isA) {                                                                            \
            unsigned _d = smem_u32(&As[st][t][0]);                                            \
            const __nv_bfloat16* _p = Ap + (ks) * KSTEP;                                      \
            CPA6(_d, _p);                                                                     \
        } else {                                                                              \
            unsigned _d0 = smem_u32(&Bs[st][u][0]);                                           \
            const __nv_bfloat16* _p0 = Wp0 + (ks) * KSTEP;                                    \
            CPA6(_d0, _p0);                                                                   \
            if (u < 32) {                                                                     \
                unsigned _d1 = smem_u32(&Bs[st][64 + u][0]);                                  \
                const __nv_bfloat16* _p1 = Wp1 + (ks) * KSTEP;                                \
                CPA6(_d1, _p1);                                                               \
            }                                                                                 \
        }                                                                                     \
        asm volatile("cp.async.commit_group;\n");                                             \
    } while (0)

    LOAD_STAGE(0, 0);
    LOAD_STAGE(1, 1);

    const int r16 = lane & 15, chh = lane >> 4;

    for (int ks = 0; ks < nk; ks++) {
        if (ks + 1 < nk) asm volatile("cp.async.wait_group 1;\n");
        else             asm volatile("cp.async.wait_group 0;\n");
        __syncthreads();

        if (ks + 2 < nk) {
            int st = (ks + 2) % NSTG;
            LOAD_STAGE(st, ks + 2);
        }

        const int buf = ks % NSTG;
#pragma unroll
        for (int kk = 0; kk < 3; kk++) {
            unsigned a[4][4], b[2][4];
#pragma unroll
            for (int i = 0; i < 4; i++) {
                unsigned addr = smem_u32(&As[buf][wm * 64 + i * 16 + r16][kk * 16 + chh * 8]);
                asm volatile("ldmatrix.sync.aligned.m8n8.x4.shared.b16 {%0,%1,%2,%3}, [%4];"
                    : "=r"(a[i][0]), "=r"(a[i][1]), "=r"(a[i][2]), "=r"(a[i][3]) : "r"(addr));
            }
#pragma unroll
            for (int j2 = 0; j2 < 2; j2++) {
                unsigned addr = smem_u32(&Bs[buf][wn * 32 + j2 * 16 + r16][kk * 16 + chh * 8]);
                asm volatile("ldmatrix.sync.aligned.m8n8.x4.shared.b16 {%0,%1,%2,%3}, [%4];"
                    : "=r"(b[j2][0]), "=r"(b[j2][1]), "=r"(b[j2][2]), "=r"(b[j2][3]) : "r"(addr));
            }
#pragma unroll
            for (int i = 0; i < 4; i++)
#pragma unroll
                for (int j = 0; j < 4; j++) {
                    unsigned b0 = b[j >> 1][j & 1], b1 = b[j >> 1][(j & 1) + 2];
                    asm volatile(
                        "mma.sync.aligned.m16n8k16.row.col.f32.bf16.bf16.f32 "
                        "{%0,%1,%2,%3}, {%4,%5,%6,%7}, {%8,%9}, {%0,%1,%2,%3};"
                        : "+f"(acc[i][j][0]), "+f"(acc[i][j][1]), "+f"(acc[i][j][2]), "+f"(acc[i][j][3])
                        : "r"(a[i][0]), "r"(a[i][1]), "r"(a[i][2]), "r"(a[i][3]), "r"(b0), "r"(b1));
                }
        }
    }
#undef LOAD_STAGE
#undef CPA6

    // epilogue: warp tile 64x32 at col n0 + wn*32
#pragma unroll
    for (int i = 0; i < 4; i++) {
        int rbase = m0 + wm * 64 + i * 16 + (lane >> 2);
#pragma unroll
        for (int j = 0; j < 4; j++) {
            int c = n0 + wn * 32 + j * 8 + (lane & 3) * 2;
            if (c < N) {
#pragma unroll
                for (int h = 0; h < 2; h++) {
                    int r = rbase + h * 8;
                    float v0 = acc[i][j][h * 2 + 0];
                    float v1 = acc[i][j][h * 2 + 1];
                    if (bias) { v0 += __ldg(&bias[c]); v1 += __ldg(&bias[c + 1]); }
                    if (EPI == 1) {
                        v0 = 0.5f * v0 * (1.f + erff(v0 * 0.70710678118654752f));
                        v1 = 0.5f * v1 * (1.f + erff(v1 * 0.70710678118654752f));
                    }
                    if (EPI >= 2) {
                        int orow = (EPI == 2) ? gather_row(r) : r;
                        size_t off = (size_t)orow * N + c;
                        float2 rv = *(const float2*)(res + off);
                        float2 ov; ov.x = v0 + rv.x; ov.y = v1 + rv.y;
                        *(float2*)((float*)Cout + off) = ov;
                    } else {
                        __nv_bfloat162 p;
                        p.x = __float2bfloat16(v0); p.y = __float2bfloat16(v1);
                        *(__nv_bfloat162*)((__nv_bfloat16*)Cout + (size_t)r * N + c) = p;
                    }
                }
            }
        }
    }
}

// ---------------- tensor-core windowed attention (R9, unchanged) ----------------
__device__ __forceinline__ int region(int p) { return p < 248 ? 0 : (p < 252 ? 1 : 2); }

__global__ void __launch_bounds__(128) attn_kernel(const __nv_bfloat16* __restrict__ qkv,
                                                   const float* __restrict__ rpb,
                                                   __nv_bfloat16* __restrict__ out) {
    __shared__ __nv_bfloat16 Qs[64][40];
    __shared__ __nv_bfloat16 Ks[64][40];
    __shared__ __nv_bfloat16 Vs[64][40];
    __shared__ float srpb[225];
    __shared__ int   sreg[64];

    const int win = blockIdx.x, h = blockIdx.y;
    const int t = threadIdx.x, lane = t & 31, warp = t >> 5;
    const float scale = 0.17677669529663687f;

    for (int i = t; i < 225; i += 128) srpb[i] = rpb[i * HEADS + h];
    if (t < 64) {
        int rem = win & 1023;
        int wh = rem >> 5, ww = rem & 31;
        sreg[t] = region(wh * 8 + (t >> 3)) * 3 + region(ww * 8 + (t & 7));
    }
#pragma unroll
    for (int it = 0; it < 2; it++) {
        int c = t + it * 128;
        int row = c >> 2, off = (c & 3) * 8;
        const __nv_bfloat16* src = qkv + (size_t)(win * 64 + row) * 576 + h * 32 + off;
        *(uint4*)&Qs[row][off] = *(const uint4*)(src);
        *(uint4*)&Ks[row][off] = *(const uint4*)(src + 192);
        *(uint4*)&Vs[row][off] = *(const uint4*)(src + 384);
    }
    __syncthreads();

    unsigned qa[2][4], kb[4][2][4];
    const int r16 = lane & 15, chh = lane >> 4;
#pragma unroll
    for (int kt = 0; kt < 2; kt++) {
        unsigned addr = smem_u32(&Qs[warp * 16 + r16][chh * 8 + kt * 16]);
        asm volatile("ldmatrix.sync.aligned.m8n8.x4.shared.b16 {%0,%1,%2,%3}, [%4];"
            : "=r"(qa[kt][0]), "=r"(qa[kt][1]), "=r"(qa[kt][2]), "=r"(qa[kt][3]) : "r"(addr));
    }
#pragma unroll
    for (int j2 = 0; j2 < 4; j2++)
#pragma unroll
        for (int kt = 0; kt < 2; kt++) {
            unsigned addr = smem_u32(&Ks[j2 * 16 + r16][chh * 8 + kt * 16]);
            asm volatile("ldmatrix.sync.aligned.m8n8.x4.shared.b16 {%0,%1,%2,%3}, [%4];"
                : "=r"(kb[j2][kt][0]), "=r"(kb[j2][kt][1]), "=r"(kb[j2][kt][2]), "=r"(kb[j2][kt][3]) : "r"(addr));
        }

    float s[8][4];
#pragma unroll
    for (int nt = 0; nt < 8; nt++) {
        s[nt][0] = s[nt][1] = s[nt][2] = s[nt][3] = 0.f;
        unsigned b0 = kb[nt >> 1][0][nt & 1], b1 = kb[nt >> 1][0][(nt & 1) + 2];
        asm volatile(
            "mma.sync.aligned.m16n8k16.row.col.f32.bf16.bf16.f32 "
            "{%0,%1,%2,%3}, {%4,%5,%6,%7}, {%8,%9}, {%0,%1,%2,%3};"
            : "+f"(s[nt][0]), "+f"(s[nt][1]), "+f"(s[nt][2]), "+f"(s[nt][3])
            : "r"(qa[0][0]), "r"(qa[0][1]), "r"(qa[0][2]), "r"(qa[0][3]), "r"(b0), "r"(b1));
        b0 = kb[nt >> 1][1][nt & 1]; b1 = kb[nt >> 1][1][(nt & 1) + 2];
        asm volatile(
            "mma.sync.aligned.m16n8k16.row.col.f32.bf16.bf16.f32 "
            "{%0,%1,%2,%3}, {%4,%5,%6,%7}, {%8,%9}, {%0,%1,%2,%3};"
            : "+f"(s[nt][0]), "+f"(s[nt][1]), "+f"(s[nt][2]), "+f"(s[nt][3])
            : "r"(qa[1][0]), "r"(qa[1][1]), "r"(qa[1][2]), "r"(qa[1][3]), "r"(b0), "r"(b1));
    }

    const int qi0 = warp * 16 + (lane >> 2);
    const int qi1 = qi0 + 8;
    const int ri0 = qi0 >> 3, ci0 = qi0 & 7;
    const int ri1 = qi1 >> 3, ci1 = qi1 & 7;
    const int id0 = sreg[qi0], id1 = sreg[qi1];

    float mx0 = -1e30f, mx1 = -1e30f;
#pragma unroll
    for (int nt = 0; nt < 8; nt++) {
#pragma unroll
        for (int e = 0; e < 2; e++) {
            int j = nt * 8 + (lane & 3) * 2 + e;
            int rj = j >> 3, cj = j & 7, idj = sreg[j];
            float f0 = s[nt][e]     * scale + srpb[(ri0 - rj + 7) * 15 + (ci0 - cj + 7)];
            float f1 = s[nt][e + 2] * scale + srpb[(ri1 - rj + 7) * 15 + (ci1 - cj + 7)];
            if (id0 != idj) f0 -= 100.f;
            if (id1 != idj) f1 -= 100.f;
            s[nt][e] = f0; s[nt][e + 2] = f1;
            mx0 = fmaxf(mx0, f0); mx1 = fmaxf(mx1, f1);
        }
    }
    mx0 = fmaxf(mx0, __shfl_xor_sync(0xffffffffu, mx0, 1));
    mx0 = fmaxf(mx0, __shfl_xor_sync(0xffffffffu, mx0, 2));
    mx1 = fmaxf(mx1, __shfl_xor_sync(0xffffffffu, mx1, 1));
    mx1 = fmaxf(mx1, __shfl_xor_sync(0xffffffffu, mx1, 2));

    float sum0 = 0.f, sum1 = 0.f;
#pragma unroll
    for (int nt = 0; nt < 8; nt++) {
#pragma unroll
        for (int e = 0; e < 2; e++) {
            float e0 = __expf(s[nt][e]     - mx0);
            float e1 = __expf(s[nt][e + 2] - mx1);
            s[nt][e] = e0; s[nt][e + 2] = e1;
            sum0 += e0; sum1 += e1;
        }
    }
    sum0 += __shfl_xor_sync(0xffffffffu, sum0, 1);
    sum0 += __shfl_xor_sync(0xffffffffu, sum0, 2);
    sum1 += __shfl_xor_sync(0xffffffffu, sum1, 1);
    sum1 += __shfl_xor_sync(0xffffffffu, sum1, 2);
    float inv0 = 1.f / sum0, inv1 = 1.f / sum1;

    unsigned pa[4][4];
#pragma unroll
    for (int kt = 0; kt < 4; kt++) {
        __nv_bfloat162 p;
        p = __floats2bfloat162_rn(s[2 * kt][0],     s[2 * kt][1]);     pa[kt][0] = *(unsigned*)&p;
        p = __floats2bfloat162_rn(s[2 * kt][2],     s[2 * kt][3]);     pa[kt][1] = *(unsigned*)&p;
        p = __floats2bfloat162_rn(s[2 * kt + 1][0], s[2 * kt + 1][1]); pa[kt][2] = *(unsigned*)&p;
        p = __floats2bfloat162_rn(s[2 * kt + 1][2], s[2 * kt + 1][3]); pa[kt][3] = *(unsigned*)&p;
    }

    float o[4][4];
#pragma unroll
    for (int nt = 0; nt < 4; nt++) o[nt][0] = o[nt][1] = o[nt][2] = o[nt][3] = 0.f;
#pragma unroll
    for (int kt = 0; kt < 4; kt++) {
#pragma unroll
        for (int nt = 0; nt < 4; nt++) {
            unsigned addr = smem_u32(&Vs[kt * 16 + r16][nt * 8]);
            unsigned b0, b1;
            asm volatile("ldmatrix.sync.aligned.m8n8.x2.trans.shared.b16 {%0,%1}, [%2];"
                : "=r"(b0), "=r"(b1) : "r"(addr));
            asm volatile(
                "mma.sync.aligned.m16n8k16.row.col.f32.bf16.bf16.f32 "
                "{%0,%1,%2,%3}, {%4,%5,%6,%7}, {%8,%9}, {%0,%1,%2,%3};"
                : "+f"(o[nt][0]), "+f"(o[nt][1]), "+f"(o[nt][2]), "+f"(o[nt][3])
                : "r"(pa[kt][0]), "r"(pa[kt][1]), "r"(pa[kt][2]), "r"(pa[kt][3]), "r"(b0), "r"(b1));
        }
    }

    __nv_bfloat16* op = out + (size_t)(win * 64) * CH + h * 32;
#pragma unroll
    for (int nt = 0; nt < 4; nt++) {
        int col = nt * 8 + (lane & 3) * 2;
        __nv_bfloat162 p0 = __floats2bfloat162_rn(o[nt][0] * inv0, o[nt][1] * inv0);
        __nv_bfloat162 p1 = __floats2bfloat162_rn(o[nt][2] * inv1, o[nt][3] * inv1);
        *(__nv_bfloat162*)&op[(size_t)qi0 * CH + col] = p0;
        *(__nv_bfloat162*)&op[(size_t)qi1 * CH + col] = p1;
    }
}

// ---------------- launcher ----------------
extern "C" void kernel_launch(void* const* d_in, const int* in_sizes, int n_in,
                              void* d_out, int out_size) {
    const float* x       = (const float*)d_in[0];
    const float* norm1_g = (const float*)d_in[1];
    const float* norm1_b = (const float*)d_in[2];
    const float* qkv_w   = (const float*)d_in[3];
    const float* rpb     = (const float*)d_in[4];
    const float* proj_w  = (const float*)d_in[5];
    const float* proj_b  = (const float*)d_in[6];
    const float* norm2_g = (const float*)d_in[7];
    const float* norm2_b = (const float*)d_in[8];
    const float* mlp_w1  = (const float*)d_in[9];
    const float* mlp_b1  = (const float*)d_in[10];
    const float* mlp_w2  = (const float*)d_in[11];
    const float* mlp_b2  = (const float*)d_in[12];
    float* out = (float*)d_out;

    __nv_bfloat16 *xn, *qkvb, *attnb, *h2, *hid, *wbuf;
    float* x1;
    cudaGetSymbolAddress((void**)&xn,    gb_xn);
    cudaGetSymbolAddress((void**)&qkvb,  gb_qkv);
    cudaGetSymbolAddress((void**)&attnb, gb_attn);
    cudaGetSymbolAddress((void**)&x1,    g_x1);
    cudaGetSymbolAddress((void**)&h2,    gb_h2);
    cudaGetSymbolAddress((void**)&hid,   gb_hid);
    cudaGetSymbolAddress((void**)&wbuf,  gb_w);

    __nv_bfloat16* wq = wbuf;
    __nv_bfloat16* wp = wbuf + WQ_SZ;
    __nv_bfloat16* w1 = wp   + WP_SZ;
    __nv_bfloat16* w2 = w1   + W1_SZ;

    const int M  = MTOT;
    const int MB = M / 128;         // 1024
    const int LN_BLOCKS = M / 8;

    // 1: weight conversion
    wconv_all<<<(WTOT + 255) / 256, 256>>>(qkv_w, proj_w, mlp_w1, mlp_w2, wbuf);

    // 2: LN1 -> bf16
    ln_kernel<<<LN_BLOCKS, 256>>>(x, norm1_g, norm1_b, xn, M);

    // 3: QKV GEMM (gathered rows), N = 576 = 6 x 96 exact
    gemm_mma<0, true><<<dim3(MB, 6), 192>>>(xn, wq, nullptr, nullptr, qkvb, CH, 576);

    // 4: windowed attention
    attn_kernel<<<dim3(2048, HEADS), 128>>>(qkvb, rpb, attnb);

    // 5: proj + scatter + residual -> x1 (fp32), N = 192 = 2 x 96 exact
    gemm_mma<2, false><<<dim3(MB, 2), 192>>>(attnb, wp, proj_b, x, x1, CH, 192);

    // 6: LN2 -> bf16
    ln_kernel<<<LN_BLOCKS, 256>>>(x1, norm2_g, norm2_b, h2, M);

    // 7: MLP1 (bias + exact GELU) -> bf16, N = 768 = 8 x 96 exact
    gemm_mma<1, false><<<dim3(MB, 8), 192>>>(h2, w1, mlp_b1, nullptr, hid, CH, HIDDEN);

    // 8: MLP2 (bias + residual) -> fp32 out, N = 192 = 2 x 96 exact
    gemm_mma<3, false><<<dim3(MB, 2), 192>>>(hid, w2, mlp_b2, x1, out, HIDDEN, 192);
}

// round 15
// speedup vs baseline: 1.0475x; 1.0457x over previous
#include <cuda_runtime.h>
#include <cuda_bf16.h>
#include <math.h>

// ---------------- problem constants ----------------
#define CH 192
#define HEADS 6
#define MTOT 131072
#define HIDDEN 768

// ---------------- scratch ----------------
__device__ __nv_bfloat16 gb_xn  [(size_t)MTOT * CH];
__device__ __nv_bfloat16 gb_qkv [(size_t)MTOT * 3 * CH];
__device__ __nv_bfloat16 gb_attn[(size_t)MTOT * CH];
__device__ float         g_x1   [(size_t)MTOT * CH];
__device__ __nv_bfloat16 gb_h2  [(size_t)MTOT * CH];
__device__ __nv_bfloat16 gb_hid [(size_t)MTOT * HIDDEN];
__device__ __nv_bfloat16 gb_w[576*192 + 192*192 + 768*192 + 192*768];

__device__ __forceinline__ int gather_row(int m) {
    int win = m >> 6, n = m & 63;
    int b   = win >> 10, rem = win & 1023;
    int wh  = rem >> 5,  ww  = rem & 31;
    int r   = n >> 3,    c   = n & 7;
    int hs  = (wh * 8 + r + 4) & 255;
    int ws_ = (ww * 8 + c + 4) & 255;
    return (b << 16) | (hs << 8) | ws_;
}

__device__ __forceinline__ unsigned smem_u32(const void* p) {
    return (unsigned)__cvta_generic_to_shared(p);
}

// ---------------- all weights fp32 -> bf16, ONE launch ----------------
#define WQ_SZ  110592
#define WP_SZ  36864
#define W1_SZ  147456
#define W2_SZ  147456
#define WTOT   (WQ_SZ + WP_SZ + W1_SZ + W2_SZ)

__global__ void wconv_all(const float* __restrict__ qkv_w, const float* __restrict__ proj_w,
                          const float* __restrict__ w1,    const float* __restrict__ w2,
                          __nv_bfloat16* __restrict__ out) {
    int i = blockIdx.x * 256 + threadIdx.x;
    if (i >= WTOT) return;
    const float* src; int off;
    if (i < WQ_SZ)                 { src = qkv_w;  off = i; }
    else if (i < WQ_SZ + WP_SZ)    { src = proj_w; off = i - WQ_SZ; }
    else if (i < WQ_SZ + WP_SZ + W1_SZ) { src = w1; off = i - WQ_SZ - WP_SZ; }
    else                           { src = w2;     off = i - WQ_SZ - WP_SZ - W1_SZ; }
    out[i] = __float2bfloat16(src[off]);
}

// ---------------- LayerNorm: one warp per row of 192, bf16 out ----------------
__global__ void ln_kernel(const float* __restrict__ in, const float* __restrict__ g,
                          const float* __restrict__ b, __nv_bfloat16* __restrict__ out, int M) {
    int row  = blockIdx.x * (blockDim.x >> 5) + (threadIdx.x >> 5);
    int lane = threadIdx.x & 31;
    if (row >= M) return;
    const float* rp = in + (size_t)row * CH;
    float v[6];
    float s = 0.f;
#pragma unroll
    for (int i = 0; i < 6; i++) { v[i] = rp[lane + 32 * i]; s += v[i]; }
#pragma unroll
    for (int o = 16; o; o >>= 1) s += __shfl_xor_sync(0xffffffffu, s, o);
    float mean = s * (1.f / 192.f);
    float q = 0.f;
#pragma unroll
    for (int i = 0; i < 6; i++) { float d = v[i] - mean; q += d * d; }
#pragma unroll
    for (int o = 16; o; o >>= 1) q += __shfl_xor_sync(0xffffffffu, q, o);
    float inv = rsqrtf(q * (1.f / 192.f) + 1e-5f);
    __nv_bfloat16* op = out + (size_t)row * CH;
#pragma unroll
    for (int i = 0; i < 6; i++) {
        int col = lane + 32 * i;
        op[col] = __float2bfloat16((v[i] - mean) * inv * g[col] + b[col]);
    }
}

// ---------------- HMMA bf16 GEMM: 128x96 CTA tile, 6 warps (2M x 3N), k-step 32, 3-stage ----------------
// R12-exact mainloop; grid axes swapped so consecutive CTAs share the same A block (L2 reuse).
// C[m,n] = sum_k A[m,k]*W[n,k]
// EPI: 0 = store bf16; 1 = +bias, exact GELU, bf16; 2 = scatter row, +res[gathered], fp32; 3 = +bias, +res[m], fp32
#define KSTEP 32
#define SPAD 40
#define NT 96
#define NSTG 3

template<int EPI, bool GATHER>
__global__ void __launch_bounds__(192, 3) gemm_mma(
    const __nv_bfloat16* __restrict__ A, const __nv_bfloat16* __restrict__ W,
    const float* __restrict__ bias, const float* __restrict__ res,
    void* __restrict__ Cout, int K, int N)
{
    __shared__ __nv_bfloat16 As[NSTG][128][SPAD];
    __shared__ __nv_bfloat16 Bs[NSTG][NT][SPAD];
    const int m0 = blockIdx.y * 128;      // m-block on Y (slow axis)
    const int n0 = blockIdx.x * NT;       // n-tile on X (fast axis) -> A shared across consecutive CTAs
    const int t = threadIdx.x, lane = t & 31, wid = t >> 5;
    const int wm = wid & 1, wn = wid >> 1;   // 2(M) x 3(N) warps, each 64x32

    // loaders: warps 0-3 (t<128) load A row t; warps 4-5 load B rows (u, and u+64 if u<32)
    const bool isA = (t < 128);
    const int  u   = t - 128;
    const int  arow = GATHER ? gather_row(m0 + (t & 127)) : (m0 + (t & 127));
    const __nv_bfloat16* Ap  = A + (size_t)arow * K;
    int bg0 = n0 + (u & 63);        if (bg0 >= N) bg0 = 0;
    int bg1 = n0 + 64 + (u & 31);   if (bg1 >= N) bg1 = 0;
    const __nv_bfloat16* Wp0 = W + (size_t)bg0 * K;
    const __nv_bfloat16* Wp1 = W + (size_t)bg1 * K;

    float acc[4][4][4];
#pragma unroll
    for (int i = 0; i < 4; i++)
#pragma unroll
        for (int j = 0; j < 4; j++)
#pragma unroll
            for (int q = 0; q < 4; q++) acc[i][j][q] = 0.f;

    const int nk = K / KSTEP;   // 6 (K=192) or 24 (K=768)

#define LOAD_STAGE(st, ks)                                                                    \
    do {                                                                                      \
        if (isA) {                                                                            \
            unsigned _d = smem_u32(&As[st][t][0]);                                            \
            const __nv_bfloat16* _p = Ap + (ks) * KSTEP;                                      \
            asm volatile("cp.async.cg.shared.global [%0], [%1], 16;\n" :: "r"(_d),      "l"(_p));      \
            asm volatile("cp.async.cg.shared.global [%0], [%1], 16;\n" :: "r"(_d + 16), "l"(_p + 8));  \
            asm volatile("cp.async.cg.shared.global [%0], [%1], 16;\n" :: "r"(_d + 32), "l"(_p + 16)); \
            asm volatile("cp.async.cg.shared.global [%0], [%1], 16;\n" :: "r"(_d + 48), "l"(_p + 24)); \
        } else {                                                                              \
            unsigned _d0 = smem_u32(&Bs[st][u][0]);                                           \
            const __nv_bfloat16* _p0 = Wp0 + (ks) * KSTEP;                                    \
            asm volatile("cp.async.cg.shared.global [%0], [%1], 16;\n" :: "r"(_d0),      "l"(_p0));      \
            asm volatile("cp.async.cg.shared.global [%0], [%1], 16;\n" :: "r"(_d0 + 16), "l"(_p0 + 8));  \
            asm volatile("cp.async.cg.shared.global [%0], [%1], 16;\n" :: "r"(_d0 + 32), "l"(_p0 + 16)); \
            asm volatile("cp.async.cg.shared.global [%0], [%1], 16;\n" :: "r"(_d0 + 48), "l"(_p0 + 24)); \
            if (u < 32) {                                                                     \
                unsigned _d1 = smem_u32(&Bs[st][64 + u][0]);                                  \
                const __nv_bfloat16* _p1 = Wp1 + (ks) * KSTEP;                                \
                asm volatile("cp.async.cg.shared.global [%0], [%1], 16;\n" :: "r"(_d1),      "l"(_p1));      \
                asm volatile("cp.async.cg.shared.global [%0], [%1], 16;\n" :: "r"(_d1 + 16), "l"(_p1 + 8));  \
                asm volatile("cp.async.cg.shared.global [%0], [%1], 16;\n" :: "r"(_d1 + 32), "l"(_p1 + 16)); \
                asm volatile("cp.async.cg.shared.global [%0], [%1], 16;\n" :: "r"(_d1 + 48), "l"(_p1 + 24)); \
            }                                                                                 \
        }                                                                                     \
        asm volatile("cp.async.commit_group;\n");                                             \
    } while (0)

    LOAD_STAGE(0, 0);
    LOAD_STAGE(1, 1);

    const int r16 = lane & 15, chh = lane >> 4;

    for (int ks = 0; ks < nk; ks++) {
        if (ks + 1 < nk) asm volatile("cp.async.wait_group 1;\n");
        else             asm volatile("cp.async.wait_group 0;\n");
        __syncthreads();

        if (ks + 2 < nk) {
            int st = (ks + 2) % NSTG;
            LOAD_STAGE(st, ks + 2);
        }

        const int buf = ks % NSTG;
#pragma unroll
        for (int kk = 0; kk < 2; kk++) {
            unsigned a[4][4], b[2][4];
#pragma unroll
            for (int i = 0; i < 4; i++) {
                unsigned addr = smem_u32(&As[buf][wm * 64 + i * 16 + r16][kk * 16 + chh * 8]);
                asm volatile("ldmatrix.sync.aligned.m8n8.x4.shared.b16 {%0,%1,%2,%3}, [%4];"
                    : "=r"(a[i][0]), "=r"(a[i][1]), "=r"(a[i][2]), "=r"(a[i][3]) : "r"(addr));
            }
#pragma unroll
            for (int j2 = 0; j2 < 2; j2++) {
                unsigned addr = smem_u32(&Bs[buf][wn * 32 + j2 * 16 + r16][kk * 16 + chh * 8]);
                asm volatile("ldmatrix.sync.aligned.m8n8.x4.shared.b16 {%0,%1,%2,%3}, [%4];"
                    : "=r"(b[j2][0]), "=r"(b[j2][1]), "=r"(b[j2][2]), "=r"(b[j2][3]) : "r"(addr));
            }
#pragma unroll
            for (int i = 0; i < 4; i++)
#pragma unroll
                for (int j = 0; j < 4; j++) {
                    unsigned b0 = b[j >> 1][j & 1], b1 = b[j >> 1][(j & 1) + 2];
                    asm volatile(
                        "mma.sync.aligned.m16n8k16.row.col.f32.bf16.bf16.f32 "
                        "{%0,%1,%2,%3}, {%4,%5,%6,%7}, {%8,%9}, {%0,%1,%2,%3};"
                        : "+f"(acc[i][j][0]), "+f"(acc[i][j][1]), "+f"(acc[i][j][2]), "+f"(acc[i][j][3])
                        : "r"(a[i][0]), "r"(a[i][1]), "r"(a[i][2]), "r"(a[i][3]), "r"(b0), "r"(b1));
                }
        }
    }
#undef LOAD_STAGE

    // epilogue: warp tile 64x32 at col n0 + wn*32
#pragma unroll
    for (int i = 0; i < 4; i++) {
        int rbase = m0 + wm * 64 + i * 16 + (lane >> 2);
#pragma unroll
        for (int j = 0; j < 4; j++) {
            int c = n0 + wn * 32 + j * 8 + (lane & 3) * 2;
            if (c < N) {
#pragma unroll
                for (int h = 0; h < 2; h++) {
                    int r = rbase + h * 8;
                    float v0 = acc[i][j][h * 2 + 0];
                    float v1 = acc[i][j][h * 2 + 1];
                    if (bias) { v0 += __ldg(&bias[c]); v1 += __ldg(&bias[c + 1]); }
                    if (EPI == 1) {
                        v0 = 0.5f * v0 * (1.f + erff(v0 * 0.70710678118654752f));
                        v1 = 0.5f * v1 * (1.f + erff(v1 * 0.70710678118654752f));
                    }
                    if (EPI >= 2) {
                        int orow = (EPI == 2) ? gather_row(r) : r;
                        size_t off = (size_t)orow * N + c;
                        float2 rv = *(const float2*)(res + off);
                        float2 ov; ov.x = v0 + rv.x; ov.y = v1 + rv.y;
                        *(float2*)((float*)Cout + off) = ov;
                    } else {
                        __nv_bfloat162 p;
                        p.x = __float2bfloat16(v0); p.y = __float2bfloat16(v1);
                        *(__nv_bfloat162*)((__nv_bfloat16*)Cout + (size_t)r * N + c) = p;
                    }
                }
            }
        }
    }
}

// ---------------- tensor-core windowed attention (R9, unchanged) ----------------
__device__ __forceinline__ int region(int p) { return p < 248 ? 0 : (p < 252 ? 1 : 2); }

__global__ void __launch_bounds__(128) attn_kernel(const __nv_bfloat16* __restrict__ qkv,
                                                   const float* __restrict__ rpb,
                                                   __nv_bfloat16* __restrict__ out) {
    __shared__ __nv_bfloat16 Qs[64][40];
    __shared__ __nv_bfloat16 Ks[64][40];
    __shared__ __nv_bfloat16 Vs[64][40];
    __shared__ float srpb[225];
    __shared__ int   sreg[64];

    const int win = blockIdx.x, h = blockIdx.y;
    const int t = threadIdx.x, lane = t & 31, warp = t >> 5;
    const float scale = 0.17677669529663687f;

    for (int i = t; i < 225; i += 128) srpb[i] = rpb[i * HEADS + h];
    if (t < 64) {
        int rem = win & 1023;
        int wh = rem >> 5, ww = rem & 31;
        sreg[t] = region(wh * 8 + (t >> 3)) * 3 + region(ww * 8 + (t & 7));
    }
#pragma unroll
    for (int it = 0; it < 2; it++) {
        int c = t + it * 128;
        int row = c >> 2, off = (c & 3) * 8;
        const __nv_bfloat16* src = qkv + (size_t)(win * 64 + row) * 576 + h * 32 + off;
        *(uint4*)&Qs[row][off] = *(const uint4*)(src);
        *(uint4*)&Ks[row][off] = *(const uint4*)(src + 192);
        *(uint4*)&Vs[row][off] = *(const uint4*)(src + 384);
    }
    __syncthreads();

    unsigned qa[2][4], kb[4][2][4];
    const int r16 = lane & 15, chh = lane >> 4;
#pragma unroll
    for (int kt = 0; kt < 2; kt++) {
        unsigned addr = smem_u32(&Qs[warp * 16 + r16][chh * 8 + kt * 16]);
        asm volatile("ldmatrix.sync.aligned.m8n8.x4.shared.b16 {%0,%1,%2,%3}, [%4];"
            : "=r"(qa[kt][0]), "=r"(qa[kt][1]), "=r"(qa[kt][2]), "=r"(qa[kt][3]) : "r"(addr));
    }
#pragma unroll
    for (int j2 = 0; j2 < 4; j2++)
#pragma unroll
        for (int kt = 0; kt < 2; kt++) {
            unsigned addr = smem_u32(&Ks[j2 * 16 + r16][chh * 8 + kt * 16]);
            asm volatile("ldmatrix.sync.aligned.m8n8.x4.shared.b16 {%0,%1,%2,%3}, [%4];"
                : "=r"(kb[j2][kt][0]), "=r"(kb[j2][kt][1]), "=r"(kb[j2][kt][2]), "=r"(kb[j2][kt][3]) : "r"(addr));
        }

    float s[8][4];
#pragma unroll
    for (int nt = 0; nt < 8; nt++) {
        s[nt][0] = s[nt][1] = s[nt][2] = s[nt][3] = 0.f;
        unsigned b0 = kb[nt >> 1][0][nt & 1], b1 = kb[nt >> 1][0][(nt & 1) + 2];
        asm volatile(
            "mma.sync.aligned.m16n8k16.row.col.f32.bf16.bf16.f32 "
            "{%0,%1,%2,%3}, {%4,%5,%6,%7}, {%8,%9}, {%0,%1,%2,%3};"
            : "+f"(s[nt][0]), "+f"(s[nt][1]), "+f"(s[nt][2]), "+f"(s[nt][3])
            : "r"(qa[0][0]), "r"(qa[0][1]), "r"(qa[0][2]), "r"(qa[0][3]), "r"(b0), "r"(b1));
        b0 = kb[nt >> 1][1][nt & 1]; b1 = kb[nt >> 1][1][(nt & 1) + 2];
        asm volatile(
            "mma.sync.aligned.m16n8k16.row.col.f32.bf16.bf16.f32 "
            "{%0,%1,%2,%3}, {%4,%5,%6,%7}, {%8,%9}, {%0,%1,%2,%3};"
            : "+f"(s[nt][0]), "+f"(s[nt][1]), "+f"(s[nt][2]), "+f"(s[nt][3])
            : "r"(qa[1][0]), "r"(qa[1][1]), "r"(qa[1][2]), "r"(qa[1][3]), "r"(b0), "r"(b1));
    }

    const int qi0 = warp * 16 + (lane >> 2);
    const int qi1 = qi0 + 8;
    const int ri0 = qi0 >> 3, ci0 = qi0 & 7;
    const int ri1 = qi1 >> 3, ci1 = qi1 & 7;
    const int id0 = sreg[qi0], id1 = sreg[qi1];

    float mx0 = -1e30f, mx1 = -1e30f;
#pragma unroll
    for (int nt = 0; nt < 8; nt++) {
#pragma unroll
        for (int e = 0; e < 2; e++) {
            int j = nt * 8 + (lane & 3) * 2 + e;
            int rj = j >> 3, cj = j & 7, idj = sreg[j];
            float f0 = s[nt][e]     * scale + srpb[(ri0 - rj + 7) * 15 + (ci0 - cj + 7)];
            float f1 = s[nt][e + 2] * scale + srpb[(ri1 - rj + 7) * 15 + (ci1 - cj + 7)];
            if (id0 != idj) f0 -= 100.f;
            if (id1 != idj) f1 -= 100.f;
            s[nt][e] = f0; s[nt][e + 2] = f1;
            mx0 = fmaxf(mx0, f0); mx1 = fmaxf(mx1, f1);
        }
    }
    mx0 = fmaxf(mx0, __shfl_xor_sync(0xffffffffu, mx0, 1));
    mx0 = fmaxf(mx0, __shfl_xor_sync(0xffffffffu, mx0, 2));
    mx1 = fmaxf(mx1, __shfl_xor_sync(0xffffffffu, mx1, 1));
    mx1 = fmaxf(mx1, __shfl_xor_sync(0xffffffffu, mx1, 2));

    float sum0 = 0.f, sum1 = 0.f;
#pragma unroll
    for (int nt = 0; nt < 8; nt++) {
#pragma unroll
        for (int e = 0; e < 2; e++) {
            float e0 = __expf(s[nt][e]     - mx0);
            float e1 = __expf(s[nt][e + 2] - mx1);
            s[nt][e] = e0; s[nt][e + 2] = e1;
            sum0 += e0; sum1 += e1;
        }
    }
    sum0 += __shfl_xor_sync(0xffffffffu, sum0, 1);
    sum0 += __shfl_xor_sync(0xffffffffu, sum0, 2);
    sum1 += __shfl_xor_sync(0xffffffffu, sum1, 1);
    sum1 += __shfl_xor_sync(0xffffffffu, sum1, 2);
    float inv0 = 1.f / sum0, inv1 = 1.f / sum1;

    unsigned pa[4][4];
#pragma unroll
    for (int kt = 0; kt < 4; kt++) {
        __nv_bfloat162 p;
        p = __floats2bfloat162_rn(s[2 * kt][0],     s[2 * kt][1]);     pa[kt][0] = *(unsigned*)&p;
        p = __floats2bfloat162_rn(s[2 * kt][2],     s[2 * kt][3]);     pa[kt][1] = *(unsigned*)&p;
        p = __floats2bfloat162_rn(s[2 * kt + 1][0], s[2 * kt + 1][1]); pa[kt][2] = *(unsigned*)&p;
        p = __floats2bfloat162_rn(s[2 * kt + 1][2], s[2 * kt + 1][3]); pa[kt][3] = *(unsigned*)&p;
    }

    float o[4][4];
#pragma unroll
    for (int nt = 0; nt < 4; nt++) o[nt][0] = o[nt][1] = o[nt][2] = o[nt][3] = 0.f;
#pragma unroll
    for (int kt = 0; kt < 4; kt++) {
#pragma unroll
        for (int nt = 0; nt < 4; nt++) {
            unsigned addr = smem_u32(&Vs[kt * 16 + r16][nt * 8]);
            unsigned b0, b1;
            asm volatile("ldmatrix.sync.aligned.m8n8.x2.trans.shared.b16 {%0,%1}, [%2];"
                : "=r"(b0), "=r"(b1) : "r"(addr));
            asm volatile(
                "mma.sync.aligned.m16n8k16.row.col.f32.bf16.bf16.f32 "
                "{%0,%1,%2,%3}, {%4,%5,%6,%7}, {%8,%9}, {%0,%1,%2,%3};"
                : "+f"(o[nt][0]), "+f"(o[nt][1]), "+f"(o[nt][2]), "+f"(o[nt][3])
                : "r"(pa[kt][0]), "r"(pa[kt][1]), "r"(pa[kt][2]), "r"(pa[kt][3]), "r"(b0), "r"(b1));
        }
    }

    __nv_bfloat16* op = out + (size_t)(win * 64) * CH + h * 32;
#pragma unroll
    for (int nt = 0; nt < 4; nt++) {
        int col = nt * 8 + (lane & 3) * 2;
        __nv_bfloat162 p0 = __floats2bfloat162_rn(o[nt][0] * inv0, o[nt][1] * inv0);
        __nv_bfloat162 p1 = __floats2bfloat162_rn(o[nt][2] * inv1, o[nt][3] * inv1);
        *(__nv_bfloat162*)&op[(size_t)qi0 * CH + col] = p0;
        *(__nv_bfloat162*)&op[(size_t)qi1 * CH + col] = p1;
    }
}

// ---------------- launcher ----------------
extern "C" void kernel_launch(void* const* d_in, const int* in_sizes, int n_in,
                              void* d_out, int out_size) {
    const float* x       = (const float*)d_in[0];
    const float* norm1_g = (const float*)d_in[1];
    const float* norm1_b = (const float*)d_in[2];
    const float* qkv_w   = (const float*)d_in[3];
    const float* rpb     = (const float*)d_in[4];
    const float* proj_w  = (const float*)d_in[5];
    const float* proj_b  = (const float*)d_in[6];
    const float* norm2_g = (const float*)d_in[7];
    const float* norm2_b = (const float*)d_in[8];
    const float* mlp_w1  = (const float*)d_in[9];
    const float* mlp_b1  = (const float*)d_in[10];
    const float* mlp_w2  = (const float*)d_in[11];
    const float* mlp_b2  = (const float*)d_in[12];
    float* out = (float*)d_out;

    __nv_bfloat16 *xn, *qkvb, *attnb, *h2, *hid, *wbuf;
    float* x1;
    cudaGetSymbolAddress((void**)&xn,    gb_xn);
    cudaGetSymbolAddress((void**)&qkvb,  gb_qkv);
    cudaGetSymbolAddress((void**)&attnb, gb_attn);
    cudaGetSymbolAddress((void**)&x1,    g_x1);
    cudaGetSymbolAddress((void**)&h2,    gb_h2);
    cudaGetSymbolAddress((void**)&hid,   gb_hid);
    cudaGetSymbolAddress((void**)&wbuf,  gb_w);

    __nv_bfloat16* wq = wbuf;
    __nv_bfloat16* wp = wbuf + WQ_SZ;
    __nv_bfloat16* w1 = wp   + WP_SZ;
    __nv_bfloat16* w2 = w1   + W1_SZ;

    const int M  = MTOT;
    const int MB = M / 128;         // 1024
    const int LN_BLOCKS = M / 8;

    // 1: weight conversion
    wconv_all<<<(WTOT + 255) / 256, 256>>>(qkv_w, proj_w, mlp_w1, mlp_w2, wbuf);

    // 2: LN1 -> bf16
    ln_kernel<<<LN_BLOCKS, 256>>>(x, norm1_g, norm1_b, xn, M);

    // 3: QKV GEMM (gathered rows), N = 576 = 6 x 96; n-tiles on X for A reuse
    gemm_mma<0, true><<<dim3(6, MB), 192>>>(xn, wq, nullptr, nullptr, qkvb, CH, 576);

    // 4: windowed attention
    attn_kernel<<<dim3(2048, HEADS), 128>>>(qkvb, rpb, attnb);

    // 5: proj + scatter + residual -> x1 (fp32), N = 192 = 2 x 96
    gemm_mma<2, false><<<dim3(2, MB), 192>>>(attnb, wp, proj_b, x, x1, CH, 192);

    // 6: LN2 -> bf16
    ln_kernel<<<LN_BLOCKS, 256>>>(x1, norm2_g, norm2_b, h2, M);

    // 7: MLP1 (bias + exact GELU) -> bf16, N = 768 = 8 x 96
    gemm_mma<1, false><<<dim3(8, MB), 192>>>(h2, w1, mlp_b1, nullptr, hid, CH, HIDDEN);

    // 8: MLP2 (bias + residual) -> fp32 out, N = 192 = 2 x 96
    gemm_mma<3, false><<<dim3(2, MB), 192>>>(hid, w2, mlp_b2, x1, out, HIDDEN, 192);
}